// round 6
// baseline (speedup 1.0000x reference)
#include <cuda_runtime.h>
#include <stdint.h>

// Problem geometry (fixed: act = (4, 4096, 4096) fp32)
#define DCOL 4096
#define GRP  32
#define NG   (DCOL/GRP)      // 128 groups (reduced over batch+rows+group)
#define F4_PER_ROW (DCOL/4)  // 1024 float4 per row
#define KEEP_ROWS 20         // per-block chunk tail kept L2-resident (~95 MB total)

// Scratch (__device__ globals; no allocation allowed)
__device__ unsigned int g_maxbits[NG];
__device__ unsigned int g_arrive;

// ---------------------------------------------------------------------------
__global__ void k_zero()
{
    if (threadIdx.x < NG) g_maxbits[threadIdx.x] = 0u;
    if (threadIdx.x == 0) g_arrive = 0u;
}

// ---------------------------------------------------------------------------
__device__ __forceinline__ float max4abs(float4 v)
{
    return fmaxf(fmaxf(fabsf(v.x), fabsf(v.y)), fmaxf(fabsf(v.z), fabsf(v.w)));
}

__device__ __forceinline__ float4 quant4(float4 v, float inv_s8, float s8)
{
    float4 o;
    o.x = copysignf(rintf(fminf(fabsf(v.x) * inv_s8, 8.0f)) * s8, v.x);
    o.y = copysignf(rintf(fminf(fabsf(v.y) * inv_s8, 8.0f)) * s8, v.y);
    o.z = copysignf(rintf(fminf(fabsf(v.z) * inv_s8, 8.0f)) * s8, v.z);
    o.w = copysignf(rintf(fminf(fabsf(v.w) * inv_s8, 8.0f)) * s8, v.w);
    return o;
}

// ---------------------------------------------------------------------------
// Fused persistent kernel with explicit L2 residency management.
//   Phase 1: block reduces its OWN contiguous row chunk.
//            Head rows -> __ldcs (evict-first: don't pollute L2).
//            Last KEEP_ROWS rows -> default .ca (stay L2-resident).
//   Barrier: global arrive counter (grid sized via occupancy API).
//   Phase 2: tail rows first (L2 hits), then head rows via __ldcs (stream).
//            All q stores __stcs (evict-first).
// Thread j (0..1023) owns float4-column j => fixed group g = j>>3.
// ---------------------------------------------------------------------------
__global__ __launch_bounds__(1024, 2)
void k_fused(const float4* __restrict__ act, float4* __restrict__ q,
             float* __restrict__ exps_out, int rows)
{
    const int j  = threadIdx.x;
    const int nb = gridDim.x;
    const int b  = blockIdx.x;

    // Contiguous row chunk for this block
    const int per = rows / nb;
    const int rem = rows % nb;
    const int r0  = b * per + (b < rem ? b : rem);
    const int r1  = r0 + per + (b < rem ? 1 : 0);
    int keep0 = r1 - KEEP_ROWS;
    if (keep0 < r0) keep0 = r0;

    // ---------- Phase 1: chunk max ----------
    float m = 0.0f;
    int r = r0;
    // Head: streaming loads (evict-first), unrolled x4 for MLP
    for (; r + 3 < keep0; r += 4) {
        float4 v0 = __ldcs(&act[(size_t)(r + 0) * F4_PER_ROW + j]);
        float4 v1 = __ldcs(&act[(size_t)(r + 1) * F4_PER_ROW + j]);
        float4 v2 = __ldcs(&act[(size_t)(r + 2) * F4_PER_ROW + j]);
        float4 v3 = __ldcs(&act[(size_t)(r + 3) * F4_PER_ROW + j]);
        m = fmaxf(m, fmaxf(fmaxf(max4abs(v0), max4abs(v1)),
                           fmaxf(max4abs(v2), max4abs(v3))));
    }
    for (; r < keep0; ++r)
        m = fmaxf(m, max4abs(__ldcs(&act[(size_t)r * F4_PER_ROW + j])));
    // Tail: default policy -> resident in L2 at barrier time
    for (; r + 1 < r1; r += 2) {
        float4 v0 = act[(size_t)(r + 0) * F4_PER_ROW + j];
        float4 v1 = act[(size_t)(r + 1) * F4_PER_ROW + j];
        m = fmaxf(m, fmaxf(max4abs(v0), max4abs(v1)));
    }
    for (; r < r1; ++r)
        m = fmaxf(m, max4abs(act[(size_t)r * F4_PER_ROW + j]));

    // 8-lane reduce within the group (j>>3 constant under xor 4,2,1)
    m = fmaxf(m, __shfl_xor_sync(0xffffffffu, m, 4));
    m = fmaxf(m, __shfl_xor_sync(0xffffffffu, m, 2));
    m = fmaxf(m, __shfl_xor_sync(0xffffffffu, m, 1));
    if ((j & 7) == 0)
        atomicMax(&g_maxbits[j >> 3], __float_as_uint(m));

    // ---------- Device-wide barrier ----------
    __syncthreads();
    __threadfence();
    if (j == 0) {
        atomicAdd(&g_arrive, 1u);
        while (atomicAdd(&g_arrive, 0u) < (unsigned)nb) { /* spin */ }
    }
    __syncthreads();

    // ---------- Scales (atomics live in L2; read with ldcg) ----------
    const int g = j >> 3;
    const float ma = __uint_as_float(__ldcg(&g_maxbits[g]));
    int e; float s;
    if (ma > 0.0f) {
        e = (int)((__float_as_uint(ma) >> 23) & 0xFFu) - 127;  // exact floor(log2)
        s = __uint_as_float((unsigned)(e + 127) << 23);        // 2^e exact
    } else {
        e = 0; s = 1.0f;
    }
    const float inv_s8 = 8.0f / s;     // exact power of 2
    const float s8     = s * 0.125f;   // exact power of 2

    if (b == 0 && j < NG) {
        const float ma2 = __uint_as_float(__ldcg(&g_maxbits[j]));
        exps_out[j] = (ma2 > 0.0f)
                    ? (float)((int)((__float_as_uint(ma2) >> 23) & 0xFFu) - 127)
                    : 0.0f;
    }

    // ---------- Phase 2: tail first (L2 hits), then head (stream) ----------
    int rr = r1 - 1;
    for (; rr - 1 >= keep0; rr -= 2) {
        const size_t i0 = (size_t)(rr    ) * F4_PER_ROW + j;
        const size_t i1 = (size_t)(rr - 1) * F4_PER_ROW + j;
        float4 v0 = act[i0];
        float4 v1 = act[i1];
        __stcs(&q[i0], quant4(v0, inv_s8, s8));
        __stcs(&q[i1], quant4(v1, inv_s8, s8));
    }
    for (; rr >= keep0; --rr) {
        const size_t i0 = (size_t)rr * F4_PER_ROW + j;
        __stcs(&q[i0], quant4(act[i0], inv_s8, s8));
    }
    // Head: forward order, streaming reads
    int h = r0;
    for (; h + 1 < keep0; h += 2) {
        const size_t i0 = (size_t)(h    ) * F4_PER_ROW + j;
        const size_t i1 = (size_t)(h + 1) * F4_PER_ROW + j;
        float4 v0 = __ldcs(&act[i0]);
        float4 v1 = __ldcs(&act[i1]);
        __stcs(&q[i0], quant4(v0, inv_s8, s8));
        __stcs(&q[i1], quant4(v1, inv_s8, s8));
    }
    for (; h < keep0; ++h) {
        const size_t i0 = (size_t)h * F4_PER_ROW + j;
        __stcs(&q[i0], quant4(__ldcs(&act[i0]), inv_s8, s8));
    }
}

// ---------------------------------------------------------------------------
extern "C" void kernel_launch(void* const* d_in, const int* in_sizes, int n_in,
                              void* d_out, int out_size)
{
    const float4* act = (const float4*)d_in[0];
    float*        out = (float*)d_out;
    const int total = in_sizes[0];   // 67108864
    const int rows  = total / DCOL;  // 16384

    // Grid sized to guaranteed co-residency (spin barrier safety)
    int dev = 0, numSMs = 148, bpm = 2;
    cudaGetDevice(&dev);
    cudaDeviceGetAttribute(&numSMs, cudaDevAttrMultiProcessorCount, dev);
    cudaOccupancyMaxActiveBlocksPerMultiprocessor(&bpm, k_fused, 1024, 0);
    if (bpm < 1) bpm = 1;
    int grid = numSMs * bpm;
    if (grid > rows) grid = rows;

    k_zero<<<1, 128>>>();
    k_fused<<<grid, 1024>>>(act, (float4*)d_out, out + (size_t)total, rows);
}